// round 1
// baseline (speedup 1.0000x reference)
#include <cuda_runtime.h>

#define BATCH 32
#define L 1024
#define HD 1024

// ---------------- scratch (static device memory; no allocations) ----------------
static __device__ float g_S  [(size_t)BATCH * L * L];   // masked scores
static __device__ float g_Pb [(size_t)BATCH * L * L];   // row-softmax probs (attn_b)
static __device__ float g_PaT[(size_t)BATCH * L * L];   // col-softmax probs, transposed (attn_a^T)
static __device__ float g_rmax[BATCH * L];
static __device__ float g_rinv[BATCH * L];
static __device__ float g_cmax[BATCH * L];
static __device__ float g_cinv[BATCH * L];

// ---------------- GEMM 1: S[b,s,t] = mask ? (a[b,s,:] . b[b,t,:]) * temp : -1e4 ----
// NT gemm: both operands row-major [L, HD], K-dim = h (contiguous for both).
__global__ __launch_bounds__(256) void gemm_nt_mask(
    const float* __restrict__ A, const float* __restrict__ Bm,
    const int* __restrict__ mask_a, const int* __restrict__ mask_b,
    const float* __restrict__ temp_ptr)
{
    const int bz = blockIdx.z;
    const float* Ab = A  + (size_t)bz * L * HD;
    const float* Bb = Bm + (size_t)bz * L * HD;
    float* Cb = g_S + (size_t)bz * L * L;

    __shared__ float As[8][128];
    __shared__ float Bs[8][128];

    const int tid  = threadIdx.x;
    const int rowC = blockIdx.y * 128;
    const int colC = blockIdx.x * 128;
    const int lr = tid >> 1;            // 0..127
    const int lc = (tid & 1) * 4;       // 0 or 4
    const int ty = tid >> 4;            // 0..15
    const int tx = tid & 15;            // 0..15

    float acc[8][8];
    #pragma unroll
    for (int i = 0; i < 8; i++)
        #pragma unroll
        for (int j = 0; j < 8; j++) acc[i][j] = 0.f;

    for (int kt = 0; kt < HD; kt += 8) {
        float4 av = *(const float4*)(Ab + (size_t)(rowC + lr) * HD + kt + lc);
        float4 bv = *(const float4*)(Bb + (size_t)(colC + lr) * HD + kt + lc);
        As[lc+0][lr] = av.x; As[lc+1][lr] = av.y; As[lc+2][lr] = av.z; As[lc+3][lr] = av.w;
        Bs[lc+0][lr] = bv.x; Bs[lc+1][lr] = bv.y; Bs[lc+2][lr] = bv.z; Bs[lc+3][lr] = bv.w;
        __syncthreads();
        #pragma unroll
        for (int k = 0; k < 8; k++) {
            float ra[8], rb[8];
            #pragma unroll
            for (int i = 0; i < 8; i++) ra[i] = As[k][ty * 8 + i];
            #pragma unroll
            for (int j = 0; j < 8; j++) rb[j] = Bs[k][tx * 8 + j];
            #pragma unroll
            for (int i = 0; i < 8; i++)
                #pragma unroll
                for (int j = 0; j < 8; j++)
                    acc[i][j] = fmaf(ra[i], rb[j], acc[i][j]);
        }
        __syncthreads();
    }

    const float temp = *temp_ptr;
    const int r0 = rowC + ty * 8, c0 = colC + tx * 8;
    int mav[8], mbv[8];
    #pragma unroll
    for (int i = 0; i < 8; i++) mav[i] = mask_a[bz * L + r0 + i];
    #pragma unroll
    for (int j = 0; j < 8; j++) mbv[j] = mask_b[bz * L + c0 + j];
    #pragma unroll
    for (int i = 0; i < 8; i++) {
        float o[8];
        #pragma unroll
        for (int j = 0; j < 8; j++)
            o[j] = (mav[i] && mbv[j]) ? acc[i][j] * temp : -10000.0f;
        *(float4*)(Cb + (size_t)(r0 + i) * L + c0)     = make_float4(o[0], o[1], o[2], o[3]);
        *(float4*)(Cb + (size_t)(r0 + i) * L + c0 + 4) = make_float4(o[4], o[5], o[6], o[7]);
    }
}

// ---------------- row softmax stats (over t, per (b,s)) -----------------------
__global__ __launch_bounds__(256) void row_stats_kernel()
{
    const int row = blockIdx.x;  // 0 .. BATCH*L-1
    const float4* p = (const float4*)(g_S + (size_t)row * L);
    const int tid = threadIdx.x;
    float4 v = p[tid];
    float m = fmaxf(fmaxf(v.x, v.y), fmaxf(v.z, v.w));
    __shared__ float red[256];
    red[tid] = m; __syncthreads();
    #pragma unroll
    for (int s = 128; s > 0; s >>= 1) {
        if (tid < s) red[tid] = fmaxf(red[tid], red[tid + s]);
        __syncthreads();
    }
    m = red[0];
    __syncthreads();
    float e = expf(v.x - m) + expf(v.y - m) + expf(v.z - m) + expf(v.w - m);
    red[tid] = e; __syncthreads();
    #pragma unroll
    for (int s = 128; s > 0; s >>= 1) {
        if (tid < s) red[tid] += red[tid + s];
        __syncthreads();
    }
    if (tid == 0) { g_rmax[row] = m; g_rinv[row] = 1.0f / red[0]; }
}

// ---------------- col softmax stats (over s, per (b,t)), online ----------------
__global__ __launch_bounds__(256) void col_stats_kernel()
{
    const int b = blockIdx.y;
    const int t = blockIdx.x * 256 + threadIdx.x;
    const float* p = g_S + (size_t)b * L * L + t;
    float m = -1e30f;
    float l = 0.f;
    #pragma unroll 8
    for (int s = 0; s < L; s++) {
        float x = p[(size_t)s * L];
        float nm = fmaxf(m, x);
        l = l * expf(m - nm) + expf(x - nm);
        m = nm;
    }
    g_cmax[b * L + t] = m;
    g_cinv[b * L + t] = 1.0f / l;
}

// ------- probabilities: Pb (direct) and PaT (transposed via smem tile) ---------
__global__ __launch_bounds__(256) void probs_kernel()
{
    const int b  = blockIdx.z;
    const int t0 = blockIdx.x * 32;
    const int s0 = blockIdx.y * 32;
    const int tx = threadIdx.x & 31;
    const int ty = threadIdx.x >> 5;   // 0..7
    __shared__ float tile[32][33];
    const float* Sb = g_S + (size_t)b * L * L;
    const float cm = g_cmax[b * L + t0 + tx];
    const float ci = g_cinv[b * L + t0 + tx];
    #pragma unroll
    for (int r = 0; r < 4; r++) {
        const int s = s0 + ty + r * 8;
        float x = Sb[(size_t)s * L + t0 + tx];
        float pb = expf(x - g_rmax[b * L + s]) * g_rinv[b * L + s];
        g_Pb[(size_t)b * L * L + (size_t)s * L + t0 + tx] = pb;
        tile[ty + r * 8][tx] = expf(x - cm) * ci;
    }
    __syncthreads();
    #pragma unroll
    for (int r = 0; r < 4; r++) {
        const int t = t0 + ty + r * 8;
        g_PaT[(size_t)b * L * L + (size_t)t * L + s0 + tx] = tile[tx][ty + r * 8];
    }
}

// ---------------- GEMM 2/3: C[b] = P[b] @ Bin[b]  (NN, M=N=K=1024) -------------
// SRC==0: A = g_Pb (feature_a = attn_b @ b), SRC==1: A = g_PaT (feature_b = attn_a^T @ a)
template <int SRC>
__global__ __launch_bounds__(256) void gemm_nn(
    const float* __restrict__ Bin, float* __restrict__ Cout)
{
    const int bz = blockIdx.z;
    const float* Ab = (SRC == 0 ? g_Pb : g_PaT) + (size_t)bz * L * L;
    const float* Bb = Bin + (size_t)bz * L * HD;
    float* Cb = Cout + (size_t)bz * L * HD;

    __shared__ float As[8][128];
    __shared__ float Bs[8][128];

    const int tid  = threadIdx.x;
    const int rowC = blockIdx.y * 128;
    const int colC = blockIdx.x * 128;
    const int lr = tid >> 1;
    const int lc = (tid & 1) * 4;
    const int bk = tid >> 5;            // 0..7
    const int bcol = (tid & 31) * 4;    // 0..124
    const int ty = tid >> 4;
    const int tx = tid & 15;

    float acc[8][8];
    #pragma unroll
    for (int i = 0; i < 8; i++)
        #pragma unroll
        for (int j = 0; j < 8; j++) acc[i][j] = 0.f;

    for (int kt = 0; kt < L; kt += 8) {
        float4 av = *(const float4*)(Ab + (size_t)(rowC + lr) * L + kt + lc);
        float4 bv = *(const float4*)(Bb + (size_t)(kt + bk) * HD + colC + bcol);
        As[lc+0][lr] = av.x; As[lc+1][lr] = av.y; As[lc+2][lr] = av.z; As[lc+3][lr] = av.w;
        *(float4*)&Bs[bk][bcol] = bv;
        __syncthreads();
        #pragma unroll
        for (int k = 0; k < 8; k++) {
            float ra[8], rb[8];
            #pragma unroll
            for (int i = 0; i < 8; i++) ra[i] = As[k][ty * 8 + i];
            #pragma unroll
            for (int j = 0; j < 8; j++) rb[j] = Bs[k][tx * 8 + j];
            #pragma unroll
            for (int i = 0; i < 8; i++)
                #pragma unroll
                for (int j = 0; j < 8; j++)
                    acc[i][j] = fmaf(ra[i], rb[j], acc[i][j]);
        }
        __syncthreads();
    }

    const int r0 = rowC + ty * 8, c0 = colC + tx * 8;
    #pragma unroll
    for (int i = 0; i < 8; i++) {
        *(float4*)(Cb + (size_t)(r0 + i) * HD + c0)     =
            make_float4(acc[i][0], acc[i][1], acc[i][2], acc[i][3]);
        *(float4*)(Cb + (size_t)(r0 + i) * HD + c0 + 4) =
            make_float4(acc[i][4], acc[i][5], acc[i][6], acc[i][7]);
    }
}

// ---------------- launch --------------------------------------------------------
extern "C" void kernel_launch(void* const* d_in, const int* in_sizes, int n_in,
                              void* d_out, int out_size)
{
    const float* a    = (const float*)d_in[0];
    const float* b    = (const float*)d_in[1];
    const int*   ma   = (const int*)d_in[2];
    const int*   mb   = (const int*)d_in[3];
    const float* temp = (const float*)d_in[4];

    float* fa = (float*)d_out;                      // feature_a [B, La, H]
    float* fb = fa + (size_t)BATCH * L * HD;        // feature_b [B, Lb, H]

    dim3 blk(256);
    dim3 gGemm(HD / 128, L / 128, BATCH);

    gemm_nt_mask<<<gGemm, blk>>>(a, b, ma, mb, temp);
    row_stats_kernel<<<BATCH * L, 256>>>();
    col_stats_kernel<<<dim3(L / 256, BATCH), 256>>>();
    probs_kernel<<<dim3(L / 32, L / 32, BATCH), 256>>>();
    gemm_nn<0><<<gGemm, blk>>>(b, fa);
    gemm_nn<1><<<gGemm, blk>>>(a, fb);
}

// round 3
// speedup vs baseline: 2.1065x; 2.1065x over previous
#include <cuda_runtime.h>
#include <cuda_bf16.h>
#include <cstdint>

#define BATCH 32
#define L 1024
#define HD 1024

// ---------------- scratch (static device memory; no allocations) ----------------
static __device__ float g_S  [(size_t)BATCH * L * L];   // masked scores
static __device__ float g_Pb [(size_t)BATCH * L * L];   // row-softmax probs (attn_b)
static __device__ float g_PaT[(size_t)BATCH * L * L];   // col-softmax probs (attn_a^T)
static __device__ float g_aT [(size_t)BATCH * L * HD];  // a transposed [b][h][s]
static __device__ float g_bT [(size_t)BATCH * L * HD];  // b transposed [b][h][t]
static __device__ float g_rmax[BATCH * L];
static __device__ float g_rinv[BATCH * L];
static __device__ float g_cmax[BATCH * L];
static __device__ float g_cinv[BATCH * L];

// ================= warp-MMA helpers (base-arch PTX, no tcgen05) =================
__device__ __forceinline__ uint32_t smem_u32(const void* p) {
    uint32_t a;
    asm("{ .reg .u64 t; cvta.to.shared.u64 t, %1; cvt.u32.u64 %0, t; }" : "=r"(a) : "l"(p));
    return a;
}
__device__ __forceinline__ void ldm_x4(uint32_t* r, uint32_t addr) {
    asm volatile("ldmatrix.sync.aligned.m8n8.x4.shared.b16 {%0,%1,%2,%3}, [%4];"
        : "=r"(r[0]), "=r"(r[1]), "=r"(r[2]), "=r"(r[3]) : "r"(addr));
}
__device__ __forceinline__ void mma16816(float* c, const uint32_t* a, const uint32_t* b) {
    asm volatile("mma.sync.aligned.m16n8k16.row.col.f32.bf16.bf16.f32 "
        "{%0,%1,%2,%3}, {%4,%5,%6,%7}, {%8,%9}, {%0,%1,%2,%3};"
        : "+f"(c[0]), "+f"(c[1]), "+f"(c[2]), "+f"(c[3])
        : "r"(a[0]), "r"(a[1]), "r"(a[2]), "r"(a[3]), "r"(b[0]), "r"(b[1]));
}
// split 2 floats into packed bf16 hi pair + lo pair
__device__ __forceinline__ void split2(float x, float y, uint32_t& h, uint32_t& l) {
    __nv_bfloat162 hh;
    hh.x = __float2bfloat16(x); hh.y = __float2bfloat16(y);
    float rx = x - __bfloat162float(hh.x);
    float ry = y - __bfloat162float(hh.y);
    __nv_bfloat162 ll;
    ll.x = __float2bfloat16(rx); ll.y = __float2bfloat16(ry);
    h = *(uint32_t*)&hh; l = *(uint32_t*)&ll;
}

// Load 128x32 fp32 tile -> SMEM 128 rows x 64 bf16 (cols 0-31 hi, 32-63 lo),
// 128B rows, 16B-chunk XOR swizzle: phys_chunk = chunk ^ (row & 7).
__device__ __forceinline__ void stage_tile(const float* __restrict__ gsrc, char* sdst,
                                           int tid, int kt) {
    const int row = tid >> 1;
    const int gb  = (tid & 1) * 2;          // group base (group = 8 floats = 16B bf16 chunk)
    const float4* src = (const float4*)(gsrc + (size_t)row * 1024 + kt + gb * 8);
    float4 v0 = src[0], v1 = src[1], v2 = src[2], v3 = src[3];
    char* rbase = sdst + row * 128;
    const int rx = row & 7;
    uint32_t h[4], l[4];
    split2(v0.x, v0.y, h[0], l[0]); split2(v0.z, v0.w, h[1], l[1]);
    split2(v1.x, v1.y, h[2], l[2]); split2(v1.z, v1.w, h[3], l[3]);
    *(uint4*)(rbase + (( gb      ^ rx) * 16)) = make_uint4(h[0], h[1], h[2], h[3]);
    *(uint4*)(rbase + (((gb + 4) ^ rx) * 16)) = make_uint4(l[0], l[1], l[2], l[3]);
    split2(v2.x, v2.y, h[0], l[0]); split2(v2.z, v2.w, h[1], l[1]);
    split2(v3.x, v3.y, h[2], l[2]); split2(v3.z, v3.w, h[3], l[3]);
    *(uint4*)(rbase + (((gb + 1) ^ rx) * 16)) = make_uint4(h[0], h[1], h[2], h[3]);
    *(uint4*)(rbase + (((gb + 5) ^ rx) * 16)) = make_uint4(l[0], l[1], l[2], l[3]);
}

// ================= bf16-split warp-MMA GEMM: C[b] = A[b] @ B[b]^T ===============
// A, B: [1024 x 1024] fp32 K-major. EPI 0: mask+temperature (scores). EPI 1: plain.
template <int EPI>
__global__ __launch_bounds__(256) void gemm_tc(
    const float* __restrict__ A, const float* __restrict__ Bm, float* __restrict__ C,
    const int* __restrict__ mask_a, const int* __restrict__ mask_b,
    const float* __restrict__ temp_ptr)
{
    extern __shared__ char sm[];
    const int tid = threadIdx.x;
    const int wid = tid >> 5;
    const int l   = tid & 31;
    const int bz  = blockIdx.z;
    const int rowC = blockIdx.y * 128;
    const int colC = blockIdx.x * 128;

    char* bufA[2] = { sm,         sm + 32768 };
    char* bufB[2] = { sm + 16384, sm + 49152 };

    const float* gA = A  + ((size_t)bz << 20) + ((size_t)rowC << 10);
    const float* gB = Bm + ((size_t)bz << 20) + ((size_t)colC << 10);

    const int wr = wid & 3;          // warp m index (4)
    const int wc = wid >> 2;         // warp n index (2)
    const int m0 = wr * 32;
    const int n0 = wc * 64;

    float acc[2][8][4];
    #pragma unroll
    for (int i = 0; i < 2; i++)
        #pragma unroll
        for (int j = 0; j < 8; j++)
            #pragma unroll
            for (int k = 0; k < 4; k++) acc[i][j][k] = 0.f;

    // ldmatrix lane addressing components
    const int lrA = l & 15;               // row within 16
    const int lcA = l >> 4;               // +chunk
    const int lrB = (l & 7) + ((l & 16) >> 1);
    const int lcB = (l >> 3) & 1;

    stage_tile(gA, bufA[0], tid, 0);
    stage_tile(gB, bufB[0], tid, 0);
    __syncthreads();

    for (int s = 0; s < 32; ++s) {
        const int cur = s & 1;
        // prefetch+stage next K-slab into the other buffer (LDGs issue before MMAs)
        if (s < 31) {
            stage_tile(gA, bufA[cur ^ 1], tid, (s + 1) * 32);
            stage_tile(gB, bufB[cur ^ 1], tid, (s + 1) * 32);
        }
        const uint32_t sAb = smem_u32(bufA[cur]);
        const uint32_t sBb = smem_u32(bufB[cur]);
        #pragma unroll
        for (int kc = 0; kc < 4; kc += 2) {      // two k16 steps; chunks: hi kc,kc+1 / lo kc+4,kc+5
            uint32_t a_hi[2][4], a_lo[2][4];
            #pragma unroll
            for (int mi = 0; mi < 2; ++mi) {
                const int r = m0 + mi * 16 + lrA;
                const int rx = r & 7;
                ldm_x4(a_hi[mi], sAb + r * 128 + (((kc     + lcA) ^ rx) * 16));
                ldm_x4(a_lo[mi], sAb + r * 128 + (((kc + 4 + lcA) ^ rx) * 16));
            }
            #pragma unroll
            for (int nh = 0; nh < 2; ++nh) {
                uint32_t b_hi[2][4], b_lo[2][4];
                #pragma unroll
                for (int nt = 0; nt < 2; ++nt) {
                    const int r = n0 + nh * 32 + nt * 16 + lrB;
                    const int rx = r & 7;
                    ldm_x4(b_hi[nt], sBb + r * 128 + (((kc     + lcB) ^ rx) * 16));
                    ldm_x4(b_lo[nt], sBb + r * 128 + (((kc + 4 + lcB) ^ rx) * 16));
                }
                #pragma unroll
                for (int mi = 0; mi < 2; ++mi)
                    #pragma unroll
                    for (int nt = 0; nt < 2; ++nt)
                        #pragma unroll
                        for (int p = 0; p < 2; ++p) {
                            const int j = nh * 4 + nt * 2 + p;
                            mma16816(acc[mi][j], a_hi[mi], &b_hi[nt][p * 2]);
                            mma16816(acc[mi][j], a_hi[mi], &b_lo[nt][p * 2]);
                            mma16816(acc[mi][j], a_lo[mi], &b_hi[nt][p * 2]);
                        }
            }
        }
        __syncthreads();
    }

    // ---------------- epilogue: frags -> SMEM (swizzled) -> coalesced out ----------
    float* eb = (float*)sm;   // 128 rows x 128 floats; chunk(4f) XOR (row&7)
    #pragma unroll
    for (int mi = 0; mi < 2; ++mi)
        #pragma unroll
        for (int j = 0; j < 8; ++j) {
            const int r0 = m0 + mi * 16 + (l >> 2);
            const int col = n0 + j * 8 + (l & 3) * 2;
            const int ch = col >> 2, fo = col & 3;
            *(float2*)(eb + r0 * 128 + (ch ^ (r0 & 7)) * 4 + fo) =
                make_float2(acc[mi][j][0], acc[mi][j][1]);
            const int r1 = r0 + 8;
            *(float2*)(eb + r1 * 128 + (ch ^ (r1 & 7)) * 4 + fo) =
                make_float2(acc[mi][j][2], acc[mi][j][3]);
        }
    __syncthreads();

    float* Cb = C + ((size_t)bz << 20) + (size_t)rowC * 1024 + colC;
    const float temp = (EPI == 0) ? *temp_ptr : 0.f;
    #pragma unroll
    for (int p = 0; p < 16; ++p) {
        const int idx = p * 256 + tid;
        const int row = idx >> 5;
        const int c   = idx & 31;
        float4 v = *(float4*)(eb + row * 128 + ((c ^ (row & 7)) * 4));
        if (EPI == 0) {
            const int mav = mask_a[bz * L + rowC + row];
            const int4 mb4 = *(const int4*)(mask_b + bz * L + colC + c * 4);
            v.x = (mav && mb4.x) ? v.x * temp : -10000.0f;
            v.y = (mav && mb4.y) ? v.y * temp : -10000.0f;
            v.z = (mav && mb4.z) ? v.z * temp : -10000.0f;
            v.w = (mav && mb4.w) ? v.w * temp : -10000.0f;
        }
        *(float4*)(Cb + (size_t)row * 1024 + c * 4) = v;
    }
}

// ---------------- fp32 batched transpose: a->aT, b->bT -------------------------
__global__ __launch_bounds__(256) void transpose_kernel(
    const float* __restrict__ a, const float* __restrict__ b)
{
    __shared__ float t[32][33];
    const int z = blockIdx.z;
    const float* in;
    float* out;
    if (z < BATCH) { in = a + ((size_t)z << 20); out = g_aT + ((size_t)z << 20); }
    else           { in = b + ((size_t)(z - BATCH) << 20); out = g_bT + ((size_t)(z - BATCH) << 20); }
    const int tx = threadIdx.x & 31;
    const int ty = threadIdx.x >> 5;
    const int x0 = blockIdx.x * 32;
    const int y0 = blockIdx.y * 32;
    #pragma unroll
    for (int i = 0; i < 4; ++i)
        t[ty + i * 8][tx] = in[(size_t)(y0 + ty + i * 8) * 1024 + x0 + tx];
    __syncthreads();
    #pragma unroll
    for (int i = 0; i < 4; ++i)
        out[(size_t)(x0 + ty + i * 8) * 1024 + y0 + tx] = t[tx][ty + i * 8];
}

// ---------------- row softmax stats (over t, per (b,s)) -----------------------
__global__ __launch_bounds__(256) void row_stats_kernel()
{
    const int row = blockIdx.x;
    const float4* p = (const float4*)(g_S + (size_t)row * L);
    const int tid = threadIdx.x;
    float4 v = p[tid];
    float m = fmaxf(fmaxf(v.x, v.y), fmaxf(v.z, v.w));
    __shared__ float red[256];
    red[tid] = m; __syncthreads();
    #pragma unroll
    for (int s = 128; s > 0; s >>= 1) {
        if (tid < s) red[tid] = fmaxf(red[tid], red[tid + s]);
        __syncthreads();
    }
    m = red[0];
    __syncthreads();
    float e = expf(v.x - m) + expf(v.y - m) + expf(v.z - m) + expf(v.w - m);
    red[tid] = e; __syncthreads();
    #pragma unroll
    for (int s = 128; s > 0; s >>= 1) {
        if (tid < s) red[tid] += red[tid + s];
        __syncthreads();
    }
    if (tid == 0) { g_rmax[row] = m; g_rinv[row] = 1.0f / red[0]; }
}

// ---------------- col softmax stats (over s, per (b,t)), online ----------------
__global__ __launch_bounds__(256) void col_stats_kernel()
{
    const int b = blockIdx.y;
    const int t = blockIdx.x * 256 + threadIdx.x;
    const float* p = g_S + (size_t)b * L * L + t;
    float m = -1e30f;
    float l = 0.f;
    #pragma unroll 8
    for (int s = 0; s < L; s++) {
        float x = p[(size_t)s * L];
        float nm = fmaxf(m, x);
        l = l * expf(m - nm) + expf(x - nm);
        m = nm;
    }
    g_cmax[b * L + t] = m;
    g_cinv[b * L + t] = 1.0f / l;
}

// ------- probabilities: Pb (direct) and PaT (transposed via smem tile) ---------
__global__ __launch_bounds__(256) void probs_kernel()
{
    const int b  = blockIdx.z;
    const int t0 = blockIdx.x * 32;
    const int s0 = blockIdx.y * 32;
    const int tx = threadIdx.x & 31;
    const int ty = threadIdx.x >> 5;
    __shared__ float tile[32][33];
    const float* Sb = g_S + (size_t)b * L * L;
    const float cm = g_cmax[b * L + t0 + tx];
    const float ci = g_cinv[b * L + t0 + tx];
    #pragma unroll
    for (int r = 0; r < 4; r++) {
        const int s = s0 + ty + r * 8;
        float x = Sb[(size_t)s * L + t0 + tx];
        float pb = expf(x - g_rmax[b * L + s]) * g_rinv[b * L + s];
        g_Pb[(size_t)b * L * L + (size_t)s * L + t0 + tx] = pb;
        tile[ty + r * 8][tx] = expf(x - cm) * ci;
    }
    __syncthreads();
    #pragma unroll
    for (int r = 0; r < 4; r++) {
        const int t = t0 + ty + r * 8;
        g_PaT[(size_t)b * L * L + (size_t)t * L + s0 + tx] = tile[tx][ty + r * 8];
    }
}

// ---------------- launch --------------------------------------------------------
extern "C" void kernel_launch(void* const* d_in, const int* in_sizes, int n_in,
                              void* d_out, int out_size)
{
    const float* a    = (const float*)d_in[0];
    const float* b    = (const float*)d_in[1];
    const int*   ma   = (const int*)d_in[2];
    const int*   mb   = (const int*)d_in[3];
    const float* temp = (const float*)d_in[4];

    float* fa = (float*)d_out;
    float* fb = fa + (size_t)BATCH * L * HD;

    float* pS;   cudaGetSymbolAddress((void**)&pS,   g_S);
    float* pPb;  cudaGetSymbolAddress((void**)&pPb,  g_Pb);
    float* pPaT; cudaGetSymbolAddress((void**)&pPaT, g_PaT);
    float* paT;  cudaGetSymbolAddress((void**)&paT,  g_aT);
    float* pbT;  cudaGetSymbolAddress((void**)&pbT,  g_bT);

    const int SMEM = 65536;
    cudaFuncSetAttribute(gemm_tc<0>, cudaFuncAttributeMaxDynamicSharedMemorySize, SMEM);
    cudaFuncSetAttribute(gemm_tc<1>, cudaFuncAttributeMaxDynamicSharedMemorySize, SMEM);

    dim3 blk(256);
    dim3 gGemm(L / 128, L / 128, BATCH);

    transpose_kernel<<<dim3(32, 32, 64), blk>>>(a, b);
    gemm_tc<0><<<gGemm, blk, SMEM>>>(a, b, pS, ma, mb, temp);
    row_stats_kernel<<<BATCH * L, 256>>>();
    col_stats_kernel<<<dim3(L / 256, BATCH), 256>>>();
    probs_kernel<<<dim3(L / 32, L / 32, BATCH), 256>>>();
    gemm_tc<1><<<gGemm, blk, SMEM>>>(pPb, pbT, fa, nullptr, nullptr, nullptr);
    gemm_tc<1><<<gGemm, blk, SMEM>>>(pPaT, paT, fb, nullptr, nullptr, nullptr);
}

// round 4
// speedup vs baseline: 4.6823x; 2.2228x over previous
#include <cuda_runtime.h>
#include <cuda_bf16.h>
#include <cstdint>

#define BATCH 32
#define L 1024
#define HD 1024

// ---------------- scratch (static device memory; no allocations) ----------------
static __device__ float g_S  [(size_t)BATCH * L * L];   // compacted masked scores
static __device__ float g_Pb [(size_t)BATCH * L * L];   // compacted row-softmax probs
static __device__ float g_PaT[(size_t)BATCH * L * L];   // compacted col-softmax probs, transposed
static __device__ float g_aT [(size_t)BATCH * L * HD];  // aT_c: [b][h][i] gathered valid s
static __device__ float g_bT [(size_t)BATCH * L * HD];  // bT_c: [b][h][j] gathered valid t
static __device__ float g_rmax[BATCH * L];
static __device__ float g_rinv[BATCH * L];
static __device__ float g_cmax[BATCH * L];
static __device__ float g_cinv[BATCH * L];
static __device__ int   g_idxa[BATCH * L];
static __device__ int   g_idxb[BATCH * L];
static __device__ int   g_na[BATCH];
static __device__ int   g_nb[BATCH];
static __device__ float g_amean[BATCH * HD];            // column sums of a
static __device__ float g_bmean[BATCH * HD];            // column sums of b
static __device__ float g_cpm[8 * BATCH * L];           // col-stat partial max
static __device__ float g_cpl[8 * BATCH * L];           // col-stat partial sum
static __device__ float g_mp[8 * 2 * BATCH * HD];       // mean partials

// ================= warp-MMA helpers =================
__device__ __forceinline__ uint32_t smem_u32(const void* p) {
    uint32_t a;
    asm("{ .reg .u64 t; cvta.to.shared.u64 t, %1; cvt.u32.u64 %0, t; }" : "=r"(a) : "l"(p));
    return a;
}
__device__ __forceinline__ void ldm_x4(uint32_t* r, uint32_t addr) {
    asm volatile("ldmatrix.sync.aligned.m8n8.x4.shared.b16 {%0,%1,%2,%3}, [%4];"
        : "=r"(r[0]), "=r"(r[1]), "=r"(r[2]), "=r"(r[3]) : "r"(addr));
}
__device__ __forceinline__ void mma16816(float* c, const uint32_t* a, const uint32_t* b) {
    asm volatile("mma.sync.aligned.m16n8k16.row.col.f32.bf16.bf16.f32 "
        "{%0,%1,%2,%3}, {%4,%5,%6,%7}, {%8,%9}, {%0,%1,%2,%3};"
        : "+f"(c[0]), "+f"(c[1]), "+f"(c[2]), "+f"(c[3])
        : "r"(a[0]), "r"(a[1]), "r"(a[2]), "r"(a[3]), "r"(b[0]), "r"(b[1]));
}
__device__ __forceinline__ void split2(float x, float y, uint32_t& h, uint32_t& l) {
    __nv_bfloat162 hh;
    hh.x = __float2bfloat16(x); hh.y = __float2bfloat16(y);
    float rx = x - __bfloat162float(hh.x);
    float ry = y - __bfloat162float(hh.y);
    __nv_bfloat162 ll;
    ll.x = __float2bfloat16(rx); ll.y = __float2bfloat16(ry);
    h = *(uint32_t*)&hh; l = *(uint32_t*)&ll;
}

// Stage a 128x32 fp32 slab (optionally row-gathered) -> SMEM 128x64 bf16 (hi|lo),
// 128B rows, 16B-chunk XOR swizzle.
template <bool GATHER>
__device__ __forceinline__ void stage_g(const float* __restrict__ base,
                                        const int* __restrict__ gidx, int cnt,
                                        int row0, char* sdst, int tid, int kt) {
    const int row = tid >> 1;
    const int gb  = (tid & 1) * 2;
    int gr = row0 + row;
    if (GATHER) gr = gidx[gr < cnt ? gr : cnt - 1];
    const float4* src = (const float4*)(base + (size_t)gr * 1024 + kt + gb * 8);
    float4 v0 = src[0], v1 = src[1], v2 = src[2], v3 = src[3];
    char* rbase = sdst + row * 128;
    const int rx = row & 7;
    uint32_t h[4], l[4];
    split2(v0.x, v0.y, h[0], l[0]); split2(v0.z, v0.w, h[1], l[1]);
    split2(v1.x, v1.y, h[2], l[2]); split2(v1.z, v1.w, h[3], l[3]);
    *(uint4*)(rbase + (( gb      ^ rx) * 16)) = make_uint4(h[0], h[1], h[2], h[3]);
    *(uint4*)(rbase + (((gb + 4) ^ rx) * 16)) = make_uint4(l[0], l[1], l[2], l[3]);
    split2(v2.x, v2.y, h[0], l[0]); split2(v2.z, v2.w, h[1], l[1]);
    split2(v3.x, v3.y, h[2], l[2]); split2(v3.z, v3.w, h[3], l[3]);
    *(uint4*)(rbase + (((gb + 1) ^ rx) * 16)) = make_uint4(h[0], h[1], h[2], h[3]);
    *(uint4*)(rbase + (((gb + 5) ^ rx) * 16)) = make_uint4(l[0], l[1], l[2], l[3]);
}

// Shared mainloop: acc += A(128xK) @ B(128xK)^T over nstg K-stages of 32.
template <bool GATHER>
__device__ __forceinline__ void gemm_mainloop(
    const float* baseA, const float* baseB,
    const int* ia, const int* ib, int cntA, int cntB,
    int rowC, int colC, int nstg, char* sm, int tid, float acc[2][8][4])
{
    char* bufA[2] = { sm,         sm + 32768 };
    char* bufB[2] = { sm + 16384, sm + 49152 };
    const int wid = tid >> 5;
    const int l   = tid & 31;
    const int m0 = (wid & 3) * 32;
    const int n0 = (wid >> 2) * 64;
    const int lrA = l & 15;
    const int lcA = l >> 4;
    const int lrB = (l & 7) + ((l & 16) >> 1);
    const int lcB = (l >> 3) & 1;

    stage_g<GATHER>(baseA, ia, cntA, rowC, bufA[0], tid, 0);
    stage_g<GATHER>(baseB, ib, cntB, colC, bufB[0], tid, 0);
    __syncthreads();

    for (int s = 0; s < nstg; ++s) {
        const int cur = s & 1;
        if (s + 1 < nstg) {
            stage_g<GATHER>(baseA, ia, cntA, rowC, bufA[cur ^ 1], tid, (s + 1) * 32);
            stage_g<GATHER>(baseB, ib, cntB, colC, bufB[cur ^ 1], tid, (s + 1) * 32);
        }
        const uint32_t sAb = smem_u32(bufA[cur]);
        const uint32_t sBb = smem_u32(bufB[cur]);
        #pragma unroll
        for (int kc = 0; kc < 4; kc += 2) {
            uint32_t a_hi[2][4], a_lo[2][4];
            #pragma unroll
            for (int mi = 0; mi < 2; ++mi) {
                const int r = m0 + mi * 16 + lrA;
                const int rx = r & 7;
                ldm_x4(a_hi[mi], sAb + r * 128 + (((kc     + lcA) ^ rx) * 16));
                ldm_x4(a_lo[mi], sAb + r * 128 + (((kc + 4 + lcA) ^ rx) * 16));
            }
            #pragma unroll
            for (int nh = 0; nh < 2; ++nh) {
                uint32_t b_hi[2][4], b_lo[2][4];
                #pragma unroll
                for (int nt = 0; nt < 2; ++nt) {
                    const int r = n0 + nh * 32 + nt * 16 + lrB;
                    const int rx = r & 7;
                    ldm_x4(b_hi[nt], sBb + r * 128 + (((kc     + lcB) ^ rx) * 16));
                    ldm_x4(b_lo[nt], sBb + r * 128 + (((kc + 4 + lcB) ^ rx) * 16));
                }
                #pragma unroll
                for (int mi = 0; mi < 2; ++mi)
                    #pragma unroll
                    for (int nt = 0; nt < 2; ++nt)
                        #pragma unroll
                        for (int p = 0; p < 2; ++p) {
                            const int j = nh * 4 + nt * 2 + p;
                            mma16816(acc[mi][j], a_hi[mi], &b_hi[nt][p * 2]);
                            mma16816(acc[mi][j], a_hi[mi], &b_lo[nt][p * 2]);
                            mma16816(acc[mi][j], a_lo[mi], &b_hi[nt][p * 2]);
                        }
            }
        }
        __syncthreads();
    }
}

// Write accumulators into a swizzled SMEM epilogue buffer.
__device__ __forceinline__ void epi_stage(float* eb, const float acc[2][8][4], int tid) {
    const int wid = tid >> 5;
    const int l   = tid & 31;
    const int m0 = (wid & 3) * 32;
    const int n0 = (wid >> 2) * 64;
    #pragma unroll
    for (int mi = 0; mi < 2; ++mi)
        #pragma unroll
        for (int j = 0; j < 8; ++j) {
            const int r0 = m0 + mi * 16 + (l >> 2);
            const int col = n0 + j * 8 + (l & 3) * 2;
            const int ch = col >> 2, fo = col & 3;
            *(float2*)(eb + r0 * 128 + (ch ^ (r0 & 7)) * 4 + fo) =
                make_float2(acc[mi][j][0], acc[mi][j][1]);
            const int r1 = r0 + 8;
            *(float2*)(eb + r1 * 128 + (ch ^ (r1 & 7)) * 4 + fo) =
                make_float2(acc[mi][j][2], acc[mi][j][3]);
        }
}

// ============ GEMM 1: compacted scores S_c[i][j] = a[ia[i]].b[ib[j]]*temp ============
__global__ __launch_bounds__(256) void gemm_scores(
    const float* __restrict__ A, const float* __restrict__ Bm,
    const float* __restrict__ temp_ptr)
{
    extern __shared__ char sm[];
    const int tid = threadIdx.x;
    const int bz  = blockIdx.z;
    const int na = g_na[bz], nb = g_nb[bz];
    const int nac = (na + 127) & ~127, nbc = (nb + 127) & ~127;
    const int rowC = blockIdx.y * 128;
    const int colC = blockIdx.x * 128;
    if (rowC >= nac || colC >= nbc) return;

    float acc[2][8][4];
    #pragma unroll
    for (int i = 0; i < 2; i++)
        #pragma unroll
        for (int j = 0; j < 8; j++)
            #pragma unroll
            for (int k = 0; k < 4; k++) acc[i][j][k] = 0.f;

    gemm_mainloop<true>(A + ((size_t)bz << 20), Bm + ((size_t)bz << 20),
                        g_idxa + bz * 1024, g_idxb + bz * 1024, na, nb,
                        rowC, colC, 32, sm, tid, acc);

    float* eb = (float*)sm;
    epi_stage(eb, acc, tid);
    __syncthreads();

    float* Cb = g_S + ((size_t)bz << 20) + (size_t)rowC * 1024 + colC;
    const float temp = *temp_ptr;
    #pragma unroll
    for (int p = 0; p < 16; ++p) {
        const int idx = p * 256 + tid;
        const int row = idx >> 5;
        const int c   = idx & 31;
        float4 v = *(float4*)(eb + row * 128 + ((c ^ (row & 7)) * 4));
        const bool rv = (rowC + row) < na;
        const int cb = colC + c * 4;
        v.x = (rv && cb + 0 < nb) ? v.x * temp : -10000.0f;
        v.y = (rv && cb + 1 < nb) ? v.y * temp : -10000.0f;
        v.z = (rv && cb + 2 < nb) ? v.z * temp : -10000.0f;
        v.w = (rv && cb + 3 < nb) ? v.w * temp : -10000.0f;
        *(float4*)(Cb + (size_t)row * 1024 + c * 4) = v;
    }
}

// ============ GEMM 2/3: features = P_c @ T_c^T, scatter rows via idxM ============
__global__ __launch_bounds__(256) void gemm_feat(
    const float* __restrict__ P, const float* __restrict__ T, float* __restrict__ out,
    const int* __restrict__ cntM, const int* __restrict__ cntK,
    const int* __restrict__ idxM)
{
    extern __shared__ char sm[];
    const int tid = threadIdx.x;
    const int bz  = blockIdx.z;
    const int cm = cntM[bz], ck = cntK[bz];
    const int mc = (cm + 127) & ~127;
    const int rowC = blockIdx.y * 128;
    if (rowC >= mc) return;
    const int colC = blockIdx.x * 128;
    const int nstg = (ck + 31) >> 5;

    float acc[2][8][4];
    #pragma unroll
    for (int i = 0; i < 2; i++)
        #pragma unroll
        for (int j = 0; j < 8; j++)
            #pragma unroll
            for (int k = 0; k < 4; k++) acc[i][j][k] = 0.f;

    gemm_mainloop<false>(P + ((size_t)bz << 20), T + ((size_t)bz << 20),
                         nullptr, nullptr, 0, 0, rowC, colC, nstg, sm, tid, acc);

    float* eb = (float*)sm;
    epi_stage(eb, acc, tid);
    __syncthreads();

    const int* im = idxM + bz * 1024;
    float* Ob = out + ((size_t)bz << 20);
    #pragma unroll
    for (int p = 0; p < 16; ++p) {
        const int idx = p * 256 + tid;
        const int row = idx >> 5;
        const int c   = idx & 31;
        const int gi = rowC + row;
        if (gi < cm) {
            float4 v = *(float4*)(eb + row * 128 + ((c ^ (row & 7)) * 4));
            *(float4*)(Ob + (size_t)im[gi] * 1024 + colC + c * 4) = v;
        }
    }
}

// ---------------- mask scan: per-batch valid index lists ----------------
__global__ __launch_bounds__(256) void mask_scan(const int* __restrict__ ma,
                                                 const int* __restrict__ mb)
{
    const int b = blockIdx.x;
    const int which = blockIdx.y;
    const int* m = (which ? mb : ma) + b * 1024;
    int* idx = (which ? g_idxb : g_idxa) + b * 1024;
    const int tid = threadIdx.x;
    int4 v = ((const int4*)m)[tid];
    const int c0 = (v.x != 0), c1 = (v.y != 0), c2 = (v.z != 0), c3 = (v.w != 0);
    int s0 = c0 + c1 + c2 + c3;
    __shared__ int ps[256];
    ps[tid] = s0; __syncthreads();
    for (int off = 1; off < 256; off <<= 1) {
        int t = (tid >= off) ? ps[tid - off] : 0;
        __syncthreads();
        ps[tid] += t;
        __syncthreads();
    }
    int p = ps[tid] - s0;
    if (c0) idx[p++] = tid * 4 + 0;
    if (c1) idx[p++] = tid * 4 + 1;
    if (c2) idx[p++] = tid * 4 + 2;
    if (c3) idx[p++] = tid * 4 + 3;
    if (tid == 255) (which ? g_nb : g_na)[b] = ps[255];
}

// ---------------- column means (partials + combine, deterministic) ----------------
__global__ __launch_bounds__(256) void means_part(const float* __restrict__ a,
                                                  const float* __restrict__ bsrc)
{
    const int z = blockIdx.z;                 // 0..63: a batches then b batches
    const float* src = (z < 32 ? a : bsrc) + ((size_t)(z & 31) << 20);
    const int h = blockIdx.x * 256 + threadIdx.x;
    const int s0 = blockIdx.y * 128;
    float sum = 0.f;
    #pragma unroll 4
    for (int s = 0; s < 128; ++s)
        sum += src[(size_t)(s0 + s) * 1024 + h];
    g_mp[((size_t)blockIdx.y * 64 + z) * 1024 + h] = sum;
}
__global__ __launch_bounds__(256) void means_comb()
{
    const int z = blockIdx.y;
    const int h = blockIdx.x * 256 + threadIdx.x;
    float sum = 0.f;
    #pragma unroll
    for (int q = 0; q < 8; ++q)
        sum += g_mp[((size_t)q * 64 + z) * 1024 + h];
    float* dst = (z < 32 ? g_amean : g_bmean) + (z & 31) * 1024;
    dst[h] = sum;
}

// ---------------- gathered transpose: aT_c[h][i]=a[idx[i]][h] (zero pad to 32) ------
__global__ __launch_bounds__(256) void tgather(const float* __restrict__ a,
                                               const float* __restrict__ bsrc)
{
    const int z = blockIdx.z;
    const float* in; float* out; const int* idx; int cnt;
    if (z < 32) { in = a + ((size_t)z << 20); out = g_aT + ((size_t)z << 20);
                  idx = g_idxa + z * 1024; cnt = g_na[z]; }
    else { const int b = z - 32; in = bsrc + ((size_t)b << 20); out = g_bT + ((size_t)b << 20);
           idx = g_idxb + b * 1024; cnt = g_nb[b]; }
    const int i0 = blockIdx.y * 32;
    if (i0 >= ((cnt + 31) & ~31)) return;
    const int h0 = blockIdx.x * 32;
    __shared__ float t[32][33];
    const int tx = threadIdx.x & 31;
    const int ty = threadIdx.x >> 5;
    #pragma unroll
    for (int r = 0; r < 4; ++r) {
        const int i = i0 + ty + r * 8;
        float v = 0.f;
        if (i < cnt) v = in[(size_t)idx[i] * 1024 + h0 + tx];
        t[ty + r * 8][tx] = v;
    }
    __syncthreads();
    #pragma unroll
    for (int r = 0; r < 4; ++r)
        out[(size_t)(h0 + ty + r * 8) * 1024 + i0 + tx] = t[tx][ty + r * 8];
}

// ---------------- row softmax stats on compacted S ----------------
__global__ __launch_bounds__(256) void row_stats_c()
{
    const int b = blockIdx.y;
    const int i = blockIdx.x;
    const int nac = (g_na[b] + 127) & ~127;
    if (i >= nac) return;
    const int nbc = (g_nb[b] + 127) & ~127;
    const int row = b * 1024 + i;
    const float4* p = (const float4*)(g_S + ((size_t)b << 20) + (size_t)i * 1024);
    const int tid = threadIdx.x;
    float4 v = (tid * 4 < nbc) ? p[tid] : make_float4(-1e30f, -1e30f, -1e30f, -1e30f);
    float m = fmaxf(fmaxf(v.x, v.y), fmaxf(v.z, v.w));
    __shared__ float red[256];
    red[tid] = m; __syncthreads();
    #pragma unroll
    for (int s = 128; s > 0; s >>= 1) {
        if (tid < s) red[tid] = fmaxf(red[tid], red[tid + s]);
        __syncthreads();
    }
    m = red[0];
    __syncthreads();
    float e = expf(v.x - m) + expf(v.y - m) + expf(v.z - m) + expf(v.w - m);
    red[tid] = e; __syncthreads();
    #pragma unroll
    for (int s = 128; s > 0; s >>= 1) {
        if (tid < s) red[tid] += red[tid + s];
        __syncthreads();
    }
    if (tid == 0) { g_rmax[row] = m; g_rinv[row] = 1.0f / red[0]; }
}

// ---------------- col softmax stats: 8-way split partials + combine ----------------
__global__ __launch_bounds__(256) void col_part()
{
    const int b = blockIdx.z;
    const int nbc = (g_nb[b] + 127) & ~127;
    const int nac = (g_na[b] + 127) & ~127;
    const int t = blockIdx.x * 256 + threadIdx.x;
    const int s0 = blockIdx.y * 128;
    float m = -1e30f, l = 0.f;
    if (t < nbc && s0 < nac) {
        const float* p = g_S + ((size_t)b << 20) + t;
        const int send = min(s0 + 128, nac);
        for (int s = s0; s < send; ++s) {
            float x = p[(size_t)s << 10];
            float nm = fmaxf(m, x);
            l = l * expf(m - nm) + expf(x - nm);
            m = nm;
        }
    }
    g_cpm[(blockIdx.y * 32 + b) * 1024 + t] = m;
    g_cpl[(blockIdx.y * 32 + b) * 1024 + t] = l;
}
__global__ __launch_bounds__(256) void col_comb()
{
    const int b = blockIdx.y;
    const int t = blockIdx.x * 256 + threadIdx.x;
    float m = -1e30f, l = 0.f;
    #pragma unroll
    for (int q = 0; q < 8; ++q) {
        float pm = g_cpm[(q * 32 + b) * 1024 + t];
        float pl = g_cpl[(q * 32 + b) * 1024 + t];
        float nm = fmaxf(m, pm);
        l = l * expf(m - nm) + pl * expf(pm - nm);
        m = nm;
    }
    g_cmax[b * 1024 + t] = m;
    g_cinv[b * 1024 + t] = 1.0f / l;
}

// ------- probabilities on compacted S: Pb (direct) + PaT (transposed) ---------
__global__ __launch_bounds__(256) void probs_c()
{
    const int b  = blockIdx.z;
    const int nac = (g_na[b] + 127) & ~127;
    const int nbc = (g_nb[b] + 127) & ~127;
    const int t0 = blockIdx.x * 32;
    const int s0 = blockIdx.y * 32;
    if (s0 >= nac || t0 >= nbc) return;
    const int tx = threadIdx.x & 31;
    const int ty = threadIdx.x >> 5;
    __shared__ float tile[32][33];
    const float* Sb = g_S + ((size_t)b << 20);
    const float cm = g_cmax[b * 1024 + t0 + tx];
    const float ci = g_cinv[b * 1024 + t0 + tx];
    #pragma unroll
    for (int r = 0; r < 4; r++) {
        const int s = s0 + ty + r * 8;
        float x = Sb[(size_t)s * 1024 + t0 + tx];
        float pb = expf(x - g_rmax[b * 1024 + s]) * g_rinv[b * 1024 + s];
        g_Pb[((size_t)b << 20) + (size_t)s * 1024 + t0 + tx] = pb;
        tile[ty + r * 8][tx] = expf(x - cm) * ci;
    }
    __syncthreads();
    #pragma unroll
    for (int r = 0; r < 4; r++) {
        const int t = t0 + ty + r * 8;
        g_PaT[((size_t)b << 20) + (size_t)t * 1024 + s0 + tx] = tile[tx][ty + r * 8];
    }
}

// ------- fill invalid output rows with mean of the opposite tensor ---------
__global__ __launch_bounds__(256) void fill_invalid(const int* __restrict__ mask,
                                                    const float* __restrict__ meansum,
                                                    float* __restrict__ out)
{
    const int b = blockIdx.y;
    const int s = blockIdx.x;
    if (mask[b * 1024 + s]) return;
    const float4 v = ((const float4*)(meansum + b * 1024))[threadIdx.x];
    const float inv = 1.0f / 1024.0f;
    ((float4*)(out + ((size_t)b << 20) + (size_t)s * 1024))[threadIdx.x] =
        make_float4(v.x * inv, v.y * inv, v.z * inv, v.w * inv);
}

// ---------------- launch --------------------------------------------------------
extern "C" void kernel_launch(void* const* d_in, const int* in_sizes, int n_in,
                              void* d_out, int out_size)
{
    const float* a    = (const float*)d_in[0];
    const float* b    = (const float*)d_in[1];
    const int*   ma   = (const int*)d_in[2];
    const int*   mb   = (const int*)d_in[3];
    const float* temp = (const float*)d_in[4];

    float* fa = (float*)d_out;
    float* fb = fa + (size_t)BATCH * L * HD;

    float* pPb;  cudaGetSymbolAddress((void**)&pPb,  g_Pb);
    float* pPaT; cudaGetSymbolAddress((void**)&pPaT, g_PaT);
    float* paT;  cudaGetSymbolAddress((void**)&paT,  g_aT);
    float* pbT;  cudaGetSymbolAddress((void**)&pbT,  g_bT);
    float* pam;  cudaGetSymbolAddress((void**)&pam,  g_amean);
    float* pbm;  cudaGetSymbolAddress((void**)&pbm,  g_bmean);
    int* pna;    cudaGetSymbolAddress((void**)&pna,  g_na);
    int* pnb;    cudaGetSymbolAddress((void**)&pnb,  g_nb);
    int* pia;    cudaGetSymbolAddress((void**)&pia,  g_idxa);
    int* pib;    cudaGetSymbolAddress((void**)&pib,  g_idxb);

    const int SMEM = 65536;
    cudaFuncSetAttribute(gemm_scores, cudaFuncAttributeMaxDynamicSharedMemorySize, SMEM);
    cudaFuncSetAttribute(gemm_feat,   cudaFuncAttributeMaxDynamicSharedMemorySize, SMEM);

    dim3 blk(256);

    mask_scan<<<dim3(32, 2), blk>>>(ma, mb);
    means_part<<<dim3(4, 8, 64), blk>>>(a, b);
    means_comb<<<dim3(4, 64), blk>>>();
    tgather<<<dim3(32, 32, 64), blk>>>(a, b);
    gemm_scores<<<dim3(8, 8, 32), blk, SMEM>>>(a, b, temp);
    row_stats_c<<<dim3(1024, 32), blk>>>();
    col_part<<<dim3(4, 8, 32), blk>>>();
    col_comb<<<dim3(4, 32), blk>>>();
    probs_c<<<dim3(32, 32, 32), blk>>>();
    fill_invalid<<<dim3(1024, 32), blk>>>(ma, pbm, fa);
    fill_invalid<<<dim3(1024, 32), blk>>>(mb, pam, fb);
    gemm_feat<<<dim3(8, 8, 32), blk, SMEM>>>(pPb,  pbT, fa, pna, pnb, pia);
    gemm_feat<<<dim3(8, 8, 32), blk, SMEM>>>(pPaT, paT, fb, pnb, pna, pib);
}

// round 5
// speedup vs baseline: 5.2701x; 1.1256x over previous
#include <cuda_runtime.h>
#include <cuda_bf16.h>
#include <cstdint>

#define BATCH 32
#define L 1024
#define HD 1024

// ---------------- scratch (static device memory; no allocations) ----------------
static __device__ float g_S[(size_t)BATCH * L * L];        // compacted masked scores (fp32)
// bf16 hi|lo pre-swizzled tile buffers: [b][row][kslab][128B block]
static __device__ char g_aC  [(size_t)BATCH << 22];        // gathered a, K-major (scores A)
static __device__ char g_bC  [(size_t)BATCH << 22];        // gathered b, K-major (scores B)
static __device__ char g_aTc [(size_t)BATCH << 22];        // a^T gathered (feat-b B operand)
static __device__ char g_bTc [(size_t)BATCH << 22];        // b^T gathered (feat-a B operand)
static __device__ char g_PbC [(size_t)BATCH << 22];        // row-softmax probs (feat-a A)
static __device__ char g_PaTC[(size_t)BATCH << 22];        // col-softmax probs^T (feat-b A)
static __device__ float g_rmax[BATCH * L];
static __device__ float g_rinv[BATCH * L];
static __device__ float g_cmax[BATCH * L];
static __device__ float g_cinv[BATCH * L];
static __device__ int   g_idxa[BATCH * L];
static __device__ int   g_idxb[BATCH * L];
static __device__ int   g_na[BATCH];
static __device__ int   g_nb[BATCH];
static __device__ float g_amean[BATCH * HD];
static __device__ float g_bmean[BATCH * HD];
static __device__ float g_cpm[8 * BATCH * L];
static __device__ float g_cpl[8 * BATCH * L];
static __device__ float g_mp[8 * 2 * BATCH * HD];

// ================= helpers =================
__device__ __forceinline__ uint32_t smem_u32(const void* p) {
    uint32_t a;
    asm("{ .reg .u64 t; cvta.to.shared.u64 t, %1; cvt.u32.u64 %0, t; }" : "=r"(a) : "l"(p));
    return a;
}
__device__ __forceinline__ void ldm_x4(uint32_t* r, uint32_t addr) {
    asm volatile("ldmatrix.sync.aligned.m8n8.x4.shared.b16 {%0,%1,%2,%3}, [%4];"
        : "=r"(r[0]), "=r"(r[1]), "=r"(r[2]), "=r"(r[3]) : "r"(addr));
}
__device__ __forceinline__ void mma16816(float* c, const uint32_t* a, const uint32_t* b) {
    asm volatile("mma.sync.aligned.m16n8k16.row.col.f32.bf16.bf16.f32 "
        "{%0,%1,%2,%3}, {%4,%5,%6,%7}, {%8,%9}, {%0,%1,%2,%3};"
        : "+f"(c[0]), "+f"(c[1]), "+f"(c[2]), "+f"(c[3])
        : "r"(a[0]), "r"(a[1]), "r"(a[2]), "r"(a[3]), "r"(b[0]), "r"(b[1]));
}
__device__ __forceinline__ void split2(float x, float y, uint32_t& h, uint32_t& l) {
    __nv_bfloat162 hh;
    hh.x = __float2bfloat16(x); hh.y = __float2bfloat16(y);
    float rx = x - __bfloat162float(hh.x);
    float ry = y - __bfloat162float(hh.y);
    __nv_bfloat162 ll;
    ll.x = __float2bfloat16(rx); ll.y = __float2bfloat16(ry);
    h = *(uint32_t*)&hh; l = *(uint32_t*)&ll;
}
// pack 8 floats -> 16B of bf16 hi (lo=false) or lo residual (lo=true)
__device__ __forceinline__ uint4 pack8(const float* v, bool lo) {
    uint4 w;
    uint32_t h, l;
    split2(v[0], v[1], h, l); w.x = lo ? l : h;
    split2(v[2], v[3], h, l); w.y = lo ? l : h;
    split2(v[4], v[5], h, l); w.z = lo ? l : h;
    split2(v[6], v[7], h, l); w.w = lo ? l : h;
    return w;
}
__device__ __forceinline__ void cpa16(uint32_t dst, const void* src) {
    asm volatile("cp.async.cg.shared.global [%0], [%1], 16;" :: "r"(dst), "l"(src));
}
#define CPA_COMMIT() asm volatile("cp.async.commit_group;" ::: "memory")
#define CPA_WAIT1()  asm volatile("cp.async.wait_group 1;" ::: "memory")

// ================= unified bf16 GEMM: out = A @ B^T over pre-converted tiles =====
// A, B gmem layout per batch (4MB): [row][kslab][128B pre-swizzled hi|lo block]
// EPI 0: scores epilogue (mask counts + temperature -> g_S fp32)
// EPI 1: feature epilogue (scatter rows via idxM -> out fp32)
template <int EPI>
__global__ __launch_bounds__(256) void gemm_bf(
    const char* __restrict__ Abuf, const char* __restrict__ Bbuf,
    float* __restrict__ out,
    const int* __restrict__ cntM, const int* __restrict__ cntN,
    const int* __restrict__ idxM, const float* __restrict__ temp_ptr)
{
    extern __shared__ char sm[];
    const int tid = threadIdx.x;
    const int bz  = blockIdx.z;
    const int cm = cntM[bz];
    const int mc = (cm + 127) & ~127;
    const int rowC = blockIdx.y * 128;
    if (rowC >= mc) return;
    const int colC = blockIdx.x * 128;
    int nstg, nb = 0;
    if (EPI == 0) {
        nb = cntN[bz];
        const int nbc = (nb + 127) & ~127;
        if (colC >= nbc) return;
        nstg = 32;
    } else {
        nstg = (cntN[bz] + 31) >> 5;
    }

    const char* gA = Abuf + ((size_t)bz << 22);
    const char* gB = Bbuf + ((size_t)bz << 22);

    const int lr = tid >> 1;
    const int cb = (tid & 1) * 64;
    const uint32_t smb = smem_u32(sm);

    // staging: pure 16B async copies (layout already swizzled in gmem)
    #define ISSUE_STAGE(s) do { \
        const uint32_t _dA = smb + ((s) % 3) * 32768 + lr * 128 + cb; \
        const char* _pA = gA + (((size_t)(rowC + lr) * 32 + (s)) << 7) + cb; \
        const char* _pB = gB + (((size_t)(colC + lr) * 32 + (s)) << 7) + cb; \
        cpa16(_dA,          _pA);      cpa16(_dA + 16,         _pA + 16); \
        cpa16(_dA + 32,     _pA + 32); cpa16(_dA + 48,         _pA + 48); \
        cpa16(_dA + 16384,      _pB);      cpa16(_dA + 16384 + 16, _pB + 16); \
        cpa16(_dA + 16384 + 32, _pB + 32); cpa16(_dA + 16384 + 48, _pB + 48); \
    } while (0)

    float acc[2][8][4];
    #pragma unroll
    for (int i = 0; i < 2; i++)
        #pragma unroll
        for (int j = 0; j < 8; j++)
            #pragma unroll
            for (int k = 0; k < 4; k++) acc[i][j][k] = 0.f;

    const int wid = tid >> 5;
    const int l   = tid & 31;
    const int m0 = (wid & 3) * 32;
    const int n0 = (wid >> 2) * 64;
    const int lrA = l & 15;
    const int lcA = l >> 4;
    const int lrB = (l & 7) + ((l & 16) >> 1);
    const int lcB = (l >> 3) & 1;

    ISSUE_STAGE(0); CPA_COMMIT();
    if (nstg > 1) ISSUE_STAGE(1);
    CPA_COMMIT();

    for (int s = 0; s < nstg; ++s) {
        CPA_WAIT1();
        __syncthreads();
        if (s + 2 < nstg) ISSUE_STAGE(s + 2);
        CPA_COMMIT();

        const uint32_t sAb = smb + (s % 3) * 32768;
        const uint32_t sBb = sAb + 16384;
        #pragma unroll
        for (int kc = 0; kc < 4; kc += 2) {
            uint32_t a_hi[2][4], a_lo[2][4];
            #pragma unroll
            for (int mi = 0; mi < 2; ++mi) {
                const int r = m0 + mi * 16 + lrA;
                const int rx = r & 7;
                ldm_x4(a_hi[mi], sAb + r * 128 + (((kc     + lcA) ^ rx) * 16));
                ldm_x4(a_lo[mi], sAb + r * 128 + (((kc + 4 + lcA) ^ rx) * 16));
            }
            #pragma unroll
            for (int nh = 0; nh < 2; ++nh) {
                uint32_t b_hi[2][4], b_lo[2][4];
                #pragma unroll
                for (int nt = 0; nt < 2; ++nt) {
                    const int r = n0 + nh * 32 + nt * 16 + lrB;
                    const int rx = r & 7;
                    ldm_x4(b_hi[nt], sBb + r * 128 + (((kc     + lcB) ^ rx) * 16));
                    ldm_x4(b_lo[nt], sBb + r * 128 + (((kc + 4 + lcB) ^ rx) * 16));
                }
                #pragma unroll
                for (int mi = 0; mi < 2; ++mi)
                    #pragma unroll
                    for (int nt = 0; nt < 2; ++nt)
                        #pragma unroll
                        for (int p = 0; p < 2; ++p) {
                            const int j = nh * 4 + nt * 2 + p;
                            mma16816(acc[mi][j], a_hi[mi], &b_hi[nt][p * 2]);
                            mma16816(acc[mi][j], a_hi[mi], &b_lo[nt][p * 2]);
                            mma16816(acc[mi][j], a_lo[mi], &b_hi[nt][p * 2]);
                        }
            }
        }
    }
    __syncthreads();

    // ---------------- epilogue: frags -> SMEM (swizzled) -> coalesced out ----------
    float* eb = (float*)sm;   // 128 x 128 floats; chunk(4f) XOR (row&7)
    #pragma unroll
    for (int mi = 0; mi < 2; ++mi)
        #pragma unroll
        for (int j = 0; j < 8; ++j) {
            const int r0 = m0 + mi * 16 + (l >> 2);
            const int col = n0 + j * 8 + (l & 3) * 2;
            const int ch = col >> 2, fo = col & 3;
            *(float2*)(eb + r0 * 128 + (ch ^ (r0 & 7)) * 4 + fo) =
                make_float2(acc[mi][j][0], acc[mi][j][1]);
            const int r1 = r0 + 8;
            *(float2*)(eb + r1 * 128 + (ch ^ (r1 & 7)) * 4 + fo) =
                make_float2(acc[mi][j][2], acc[mi][j][3]);
        }
    __syncthreads();

    if (EPI == 0) {
        float* Cb = g_S + ((size_t)bz << 20) + (size_t)rowC * 1024 + colC;
        const float temp = *temp_ptr;
        #pragma unroll
        for (int p = 0; p < 16; ++p) {
            const int idx = p * 256 + tid;
            const int row = idx >> 5;
            const int c   = idx & 31;
            float4 v = *(float4*)(eb + row * 128 + ((c ^ (row & 7)) * 4));
            const bool rv = (rowC + row) < cm;
            const int cbi = colC + c * 4;
            v.x = (rv && cbi + 0 < nb) ? v.x * temp : -10000.0f;
            v.y = (rv && cbi + 1 < nb) ? v.y * temp : -10000.0f;
            v.z = (rv && cbi + 2 < nb) ? v.z * temp : -10000.0f;
            v.w = (rv && cbi + 3 < nb) ? v.w * temp : -10000.0f;
            *(float4*)(Cb + (size_t)row * 1024 + c * 4) = v;
        }
    } else {
        const int* im = idxM + bz * 1024;
        float* Ob = out + ((size_t)bz << 20);
        #pragma unroll
        for (int p = 0; p < 16; ++p) {
            const int idx = p * 256 + tid;
            const int row = idx >> 5;
            const int c   = idx & 31;
            const int gi = rowC + row;
            if (gi < cm) {
                float4 v = *(float4*)(eb + row * 128 + ((c ^ (row & 7)) * 4));
                *(float4*)(Ob + (size_t)im[gi] * 1024 + colC + c * 4) = v;
            }
        }
    }
    #undef ISSUE_STAGE
}

// ---------------- mask scan: per-batch valid index lists ----------------
__global__ __launch_bounds__(256) void mask_scan(const int* __restrict__ ma,
                                                 const int* __restrict__ mb)
{
    const int b = blockIdx.x;
    const int which = blockIdx.y;
    const int* m = (which ? mb : ma) + b * 1024;
    int* idx = (which ? g_idxb : g_idxa) + b * 1024;
    const int tid = threadIdx.x;
    int4 v = ((const int4*)m)[tid];
    const int c0 = (v.x != 0), c1 = (v.y != 0), c2 = (v.z != 0), c3 = (v.w != 0);
    int s0 = c0 + c1 + c2 + c3;
    __shared__ int ps[256];
    ps[tid] = s0; __syncthreads();
    for (int off = 1; off < 256; off <<= 1) {
        int t = (tid >= off) ? ps[tid - off] : 0;
        __syncthreads();
        ps[tid] += t;
        __syncthreads();
    }
    int p = ps[tid] - s0;
    if (c0) idx[p++] = tid * 4 + 0;
    if (c1) idx[p++] = tid * 4 + 1;
    if (c2) idx[p++] = tid * 4 + 2;
    if (c3) idx[p++] = tid * 4 + 3;
    if (tid == 255) (which ? g_nb : g_na)[b] = ps[255];
}

// ---------------- column means (partials + combine, deterministic) ----------------
__global__ __launch_bounds__(256) void means_part(const float* __restrict__ a,
                                                  const float* __restrict__ bsrc)
{
    const int z = blockIdx.z;
    const float* src = (z < 32 ? a : bsrc) + ((size_t)(z & 31) << 20);
    const int h = blockIdx.x * 256 + threadIdx.x;
    const int s0 = blockIdx.y * 128;
    float sum = 0.f;
    #pragma unroll 4
    for (int s = 0; s < 128; ++s)
        sum += src[(size_t)(s0 + s) * 1024 + h];
    g_mp[((size_t)blockIdx.y * 64 + z) * 1024 + h] = sum;
}
__global__ __launch_bounds__(256) void means_comb()
{
    const int z = blockIdx.y;
    const int h = blockIdx.x * 256 + threadIdx.x;
    float sum = 0.f;
    #pragma unroll
    for (int q = 0; q < 8; ++q)
        sum += g_mp[((size_t)q * 64 + z) * 1024 + h];
    float* dst = (z < 32 ? g_amean : g_bmean) + (z & 31) * 1024;
    dst[h] = sum;
}

// ------- conv_km: gathered rows of a/b -> bf16 hi|lo pre-swizzled K-major -------
__global__ __launch_bounds__(256) void conv_km(const float* __restrict__ a,
                                               const float* __restrict__ bsrc)
{
    const int z = blockIdx.y;
    const float* in = (z < 32 ? a : bsrc) + ((size_t)(z & 31) << 20);
    char* out = (z < 32 ? g_aC : g_bC) + ((size_t)(z & 31) << 22);
    const int* idx = (z < 32 ? g_idxa : g_idxb) + (z & 31) * 1024;
    const int cnt = (z < 32 ? g_na : g_nb)[z & 31];
    const int nc = (cnt + 127) & ~127;
    const int lin = blockIdx.x * 256 + threadIdx.x;   // row*32 + kslab
    const int row = lin >> 5;
    if (row >= nc) return;
    char* dst = out + (size_t)lin * 128;
    const int rx = row & 7;
    if (row < cnt) {
        const int ks = lin & 31;
        const float4* src = (const float4*)(in + (size_t)idx[row] * 1024 + ks * 32);
        #pragma unroll
        for (int c = 0; c < 4; ++c) {
            float4 u = src[2 * c], v = src[2 * c + 1];
            float f[8] = {u.x, u.y, u.z, u.w, v.x, v.y, v.z, v.w};
            *(uint4*)(dst + (((c    ) ^ rx) * 16)) = pack8(f, false);
            *(uint4*)(dst + (((c + 4) ^ rx) * 16)) = pack8(f, true);
        }
    } else {
        #pragma unroll
        for (int pc = 0; pc < 8; ++pc)
            *(uint4*)(dst + pc * 16) = make_uint4(0, 0, 0, 0);
    }
}

// ------- conv_t: gathered-transposed a/b -> bf16 hi|lo pre-swizzled ------------
// out rows = h (0..1023), K = compacted index j (zero-padded to 32-mult)
__global__ __launch_bounds__(256) void conv_t(const float* __restrict__ a,
                                              const float* __restrict__ bsrc)
{
    const int z = blockIdx.z;
    const float* in; char* out; const int* idx; int cnt;
    if (z < 32) { in = a + ((size_t)z << 20); out = g_aTc + ((size_t)z << 22);
                  idx = g_idxa + z * 1024; cnt = g_na[z]; }
    else { const int b = z - 32; in = bsrc + ((size_t)b << 20); out = g_bTc + ((size_t)b << 22);
           idx = g_idxb + b * 1024; cnt = g_nb[b]; }
    const int j0 = blockIdx.y * 32;
    if (j0 >= ((cnt + 31) & ~31)) return;
    const int h0 = blockIdx.x * 32;
    __shared__ float t[32][33];            // t[h_local][j_local]
    const int tx = threadIdx.x & 31;
    const int ty = threadIdx.x >> 5;
    #pragma unroll
    for (int r = 0; r < 4; ++r) {
        const int j = j0 + ty + r * 8;
        float v = (j < cnt) ? in[(size_t)idx[j] * 1024 + h0 + tx] : 0.f;
        t[tx][ty + r * 8] = v;
    }
    __syncthreads();
    const int hrow = threadIdx.x >> 3;     // 0..31
    const int c    = threadIdx.x & 7;
    const int h = h0 + hrow;
    const int ks = j0 >> 5;
    uint4 w = pack8(&t[hrow][(c & 3) * 8], c >= 4);
    *(uint4*)(out + (((size_t)h * 32 + ks) << 7) + ((c ^ (h & 7)) * 16)) = w;
}

// ---------------- row softmax stats on compacted S ----------------
__global__ __launch_bounds__(256) void row_stats_c()
{
    const int b = blockIdx.y;
    const int i = blockIdx.x;
    const int nac = (g_na[b] + 127) & ~127;
    if (i >= nac) return;
    const int nbc = (g_nb[b] + 127) & ~127;
    const int row = b * 1024 + i;
    const float4* p = (const float4*)(g_S + ((size_t)b << 20) + (size_t)i * 1024);
    const int tid = threadIdx.x;
    float4 v = (tid * 4 < nbc) ? p[tid] : make_float4(-1e30f, -1e30f, -1e30f, -1e30f);
    float m = fmaxf(fmaxf(v.x, v.y), fmaxf(v.z, v.w));
    __shared__ float red[256];
    red[tid] = m; __syncthreads();
    #pragma unroll
    for (int s = 128; s > 0; s >>= 1) {
        if (tid < s) red[tid] = fmaxf(red[tid], red[tid + s]);
        __syncthreads();
    }
    m = red[0];
    __syncthreads();
    float e = expf(v.x - m) + expf(v.y - m) + expf(v.z - m) + expf(v.w - m);
    red[tid] = e; __syncthreads();
    #pragma unroll
    for (int s = 128; s > 0; s >>= 1) {
        if (tid < s) red[tid] += red[tid + s];
        __syncthreads();
    }
    if (tid == 0) { g_rmax[row] = m; g_rinv[row] = 1.0f / red[0]; }
}

// ---------------- col softmax stats: 8-way split partials + combine ----------------
__global__ __launch_bounds__(256) void col_part()
{
    const int b = blockIdx.z;
    const int nbc = (g_nb[b] + 127) & ~127;
    const int nac = (g_na[b] + 127) & ~127;
    const int t = blockIdx.x * 256 + threadIdx.x;
    const int s0 = blockIdx.y * 128;
    float m = -1e30f, l = 0.f;
    if (t < nbc && s0 < nac) {
        const float* p = g_S + ((size_t)b << 20) + t;
        const int send = min(s0 + 128, nac);
        for (int s = s0; s < send; ++s) {
            float x = p[(size_t)s << 10];
            float nm = fmaxf(m, x);
            l = l * expf(m - nm) + expf(x - nm);
            m = nm;
        }
    }
    g_cpm[(blockIdx.y * 32 + b) * 1024 + t] = m;
    g_cpl[(blockIdx.y * 32 + b) * 1024 + t] = l;
}
__global__ __launch_bounds__(256) void col_comb()
{
    const int b = blockIdx.y;
    const int t = blockIdx.x * 256 + threadIdx.x;
    float m = -1e30f, l = 0.f;
    #pragma unroll
    for (int q = 0; q < 8; ++q) {
        float pm = g_cpm[(q * 32 + b) * 1024 + t];
        float pl = g_cpl[(q * 32 + b) * 1024 + t];
        float nm = fmaxf(m, pm);
        l = l * expf(m - nm) + pl * expf(pm - nm);
        m = nm;
    }
    g_cmax[b * 1024 + t] = m;
    g_cinv[b * 1024 + t] = 1.0f / l;
}

// ------- probabilities: write Pb and PaT directly as bf16 hi|lo pre-swizzled -------
__global__ __launch_bounds__(256) void probs_c()
{
    const int b  = blockIdx.z;
    const int nac = (g_na[b] + 127) & ~127;
    const int nbc = (g_nb[b] + 127) & ~127;
    const int t0 = blockIdx.x * 32;
    const int s0 = blockIdx.y * 32;
    if (s0 >= nac || t0 >= nbc) return;
    const int tx = threadIdx.x & 31;
    const int ty = threadIdx.x >> 5;
    __shared__ float pb[32][33];   // pb[s_local][t_local]
    __shared__ float pa[32][33];   // pa[t_local][s_local]
    const float* Sb = g_S + ((size_t)b << 20);
    const float cm = g_cmax[b * 1024 + t0 + tx];
    const float ci = g_cinv[b * 1024 + t0 + tx];
    #pragma unroll
    for (int r = 0; r < 4; r++) {
        const int s = s0 + ty + r * 8;
        float x = Sb[(size_t)s * 1024 + t0 + tx];
        pb[ty + r * 8][tx] = expf(x - g_rmax[b * 1024 + s]) * g_rinv[b * 1024 + s];
        pa[tx][ty + r * 8] = expf(x - cm) * ci;
    }
    __syncthreads();
    const int row = threadIdx.x >> 3;  // 0..31
    const int c   = threadIdx.x & 7;
    const bool lo = (c >= 4);
    {   // Pb: rows = s, kslab over t
        const int s = s0 + row;
        uint4 w = pack8(&pb[row][(c & 3) * 8], lo);
        *(uint4*)(g_PbC + ((size_t)b << 22) + (((size_t)s * 32 + (t0 >> 5)) << 7)
                  + ((c ^ (s & 7)) * 16)) = w;
    }
    {   // PaT: rows = t, kslab over s
        const int t = t0 + row;
        uint4 w = pack8(&pa[row][(c & 3) * 8], lo);
        *(uint4*)(g_PaTC + ((size_t)b << 22) + (((size_t)t * 32 + (s0 >> 5)) << 7)
                  + ((c ^ (t & 7)) * 16)) = w;
    }
}

// ------- fill invalid output rows with mean of the opposite tensor ---------
__global__ __launch_bounds__(256) void fill_invalid(const int* __restrict__ mask,
                                                    const float* __restrict__ meansum,
                                                    float* __restrict__ out)
{
    const int b = blockIdx.y;
    const int s = blockIdx.x;
    if (mask[b * 1024 + s]) return;
    const float4 v = ((const float4*)(meansum + b * 1024))[threadIdx.x];
    const float inv = 1.0f / 1024.0f;
    ((float4*)(out + ((size_t)b << 20) + (size_t)s * 1024))[threadIdx.x] =
        make_float4(v.x * inv, v.y * inv, v.z * inv, v.w * inv);
}

// ---------------- launch --------------------------------------------------------
extern "C" void kernel_launch(void* const* d_in, const int* in_sizes, int n_in,
                              void* d_out, int out_size)
{
    const float* a    = (const float*)d_in[0];
    const float* b    = (const float*)d_in[1];
    const int*   ma   = (const int*)d_in[2];
    const int*   mb   = (const int*)d_in[3];
    const float* temp = (const float*)d_in[4];

    float* fa = (float*)d_out;
    float* fb = fa + (size_t)BATCH * L * HD;

    float* pS;   cudaGetSymbolAddress((void**)&pS,   g_S);
    char* paC;   cudaGetSymbolAddress((void**)&paC,  g_aC);
    char* pbC;   cudaGetSymbolAddress((void**)&pbC,  g_bC);
    char* paTc;  cudaGetSymbolAddress((void**)&paTc, g_aTc);
    char* pbTc;  cudaGetSymbolAddress((void**)&pbTc, g_bTc);
    char* pPbC;  cudaGetSymbolAddress((void**)&pPbC, g_PbC);
    char* pPaTC; cudaGetSymbolAddress((void**)&pPaTC, g_PaTC);
    float* pam;  cudaGetSymbolAddress((void**)&pam,  g_amean);
    float* pbm;  cudaGetSymbolAddress((void**)&pbm,  g_bmean);
    int* pna;    cudaGetSymbolAddress((void**)&pna,  g_na);
    int* pnb;    cudaGetSymbolAddress((void**)&pnb,  g_nb);
    int* pia;    cudaGetSymbolAddress((void**)&pia,  g_idxa);
    int* pib;    cudaGetSymbolAddress((void**)&pib,  g_idxb);

    const int SMEM = 98304;   // 3 stages x 32KB
    cudaFuncSetAttribute(gemm_bf<0>, cudaFuncAttributeMaxDynamicSharedMemorySize, SMEM);
    cudaFuncSetAttribute(gemm_bf<1>, cudaFuncAttributeMaxDynamicSharedMemorySize, SMEM);

    dim3 blk(256);

    mask_scan<<<dim3(32, 2), blk>>>(ma, mb);
    means_part<<<dim3(4, 8, 64), blk>>>(a, b);
    means_comb<<<dim3(4, 64), blk>>>();
    conv_km<<<dim3(128, 64), blk>>>(a, b);
    conv_t<<<dim3(32, 32, 64), blk>>>(a, b);
    gemm_bf<0><<<dim3(8, 8, 32), blk, SMEM>>>(paC, pbC, pS, pna, pnb, nullptr, temp);
    row_stats_c<<<dim3(1024, 32), blk>>>();
    col_part<<<dim3(4, 8, 32), blk>>>();
    col_comb<<<dim3(4, 32), blk>>>();
    probs_c<<<dim3(32, 32, 32), blk>>>();
    fill_invalid<<<dim3(1024, 32), blk>>>(ma, pbm, fa);
    fill_invalid<<<dim3(1024, 32), blk>>>(mb, pam, fb);
    gemm_bf<1><<<dim3(8, 8, 32), blk, SMEM>>>(pPbC,  pbTc, fa, pna, pnb, pia, nullptr);
    gemm_bf<1><<<dim3(8, 8, 32), blk, SMEM>>>(pPaTC, paTc, fb, pnb, pna, pib, nullptr);
}